// round 4
// baseline (speedup 1.0000x reference)
#include <cuda_runtime.h>
#include <cuda_bf16.h>

#define N_NODES   50000
#define N_EDGES   1600000
#define F_IN      128
#define F_OUT     8
#define K_TAPS    4
#define MAX_POWER 25            // F_OUT*(K_TAPS-1)+1
#define SCAN_T    1024

#define GRID_P    148           // persistent grid: 1 CTA/SM, all co-resident
#define T_P       1024
#define ROWS_PER_CTA ((N_NODES + GRID_P - 1) / GRID_P)   // 338
#define SMEM_BYTES (N_NODES * 4)                          // 200 KB

// ---- device-global scratch (zero-initialized at module load; the scan
//      kernel restores the zero/reset invariants for graph replays) ----
__device__ float    g_s[(MAX_POWER + 1) * N_NODES];   // power vectors, 5.2 MB
__device__ int      g_cnt[N_NODES];
__device__ int      g_rowptr[N_NODES + 1];
__device__ int      g_fill[N_NODES];
__device__ int2     g_csr[N_EDGES];                   // packed {col, val-bits}
__device__ unsigned g_bar;                            // grid barrier counter

// ---------------------------------------------------------------------------
// Kernel 1: histogram of destination rows. (g_cnt == 0 at entry: invariant.)
// ---------------------------------------------------------------------------
__global__ void gfl_hist_kernel(const int* __restrict__ rows) {
    int e = blockIdx.x * blockDim.x + threadIdx.x;
    if (e < N_EDGES) atomicAdd(&g_cnt[__ldg(&rows[e])], 1);
}

// ---------------------------------------------------------------------------
// Kernel 2: single-block exclusive scan -> rowptr + fill cursors.
// Also re-zeros g_cnt and resets g_bar so the NEXT kernel_launch/replay
// sees the same initial state (graph-replay determinism).
// ---------------------------------------------------------------------------
__global__ void gfl_scan_kernel() {
    __shared__ int part[SCAN_T];
    int t = threadIdx.x;
    const int CH = (N_NODES + SCAN_T - 1) / SCAN_T;       // 49
    int beg = t * CH;
    int end = beg + CH; if (end > N_NODES) end = N_NODES;

    int s = 0;
    for (int i = beg; i < end; i++) s += g_cnt[i];
    part[t] = s;
    __syncthreads();

    #pragma unroll
    for (int off = 1; off < SCAN_T; off <<= 1) {
        int v = (t >= off) ? part[t - off] : 0;
        __syncthreads();
        part[t] += v;
        __syncthreads();
    }
    int run = (t == 0) ? 0 : part[t - 1];                 // exclusive prefix

    for (int i = beg; i < end; i++) {
        int c = g_cnt[i];
        g_rowptr[i] = run;
        g_fill[i]   = run;
        g_cnt[i]    = 0;            // restore invariant for next call
        run += c;
    }
    if (t == SCAN_T - 1) { g_rowptr[N_NODES] = run; g_bar = 0u; }
}

// ---------------------------------------------------------------------------
// Kernel 3: scatter edges into CSR slots.
// ---------------------------------------------------------------------------
__global__ void gfl_scatter_kernel(const int*   __restrict__ rows,
                                   const int*   __restrict__ cols,
                                   const float* __restrict__ vals) {
    int e = blockIdx.x * blockDim.x + threadIdx.x;
    if (e >= N_EDGES) return;
    int r   = __ldg(&rows[e]);
    int pos = atomicAdd(&g_fill[r], 1);
    int2 pk;
    pk.x = __ldg(&cols[e]);
    pk.y = __float_as_int(__ldg(&vals[e]));
    g_csr[pos] = pk;
}

// ---------------------------------------------------------------------------
// Device-wide barrier for the persistent kernel (148 co-resident CTAs).
// Monotonic counter; `it` is the 1-based barrier index within this launch.
// ---------------------------------------------------------------------------
__device__ __forceinline__ void grid_barrier(unsigned it) {
    __syncthreads();
    if (threadIdx.x == 0) {
        __threadfence();                          // publish this CTA's writes
        atomicAdd(&g_bar, 1u);
        unsigned target = it * GRID_P;
        while (atomicAdd(&g_bar, 0u) < target) __nanosleep(64);
        __threadfence();                          // acquire side
    }
    __syncthreads();
}

// ---------------------------------------------------------------------------
// Kernel 4 (persistent): rowsum -> 25x (smem fill + CSR SpMV + barrier) -> taps
// smem holds the entire current power vector (200 KB).
// ---------------------------------------------------------------------------
__global__ void __launch_bounds__(T_P, 1)
gfl_persist_kernel(const float* __restrict__ x,
                   const float* __restrict__ coeff,
                   float*       __restrict__ y) {
    extern __shared__ float sv[];                 // N_NODES floats
    const int cta  = blockIdx.x;
    const int tid  = threadIdx.x;
    const int wid  = tid >> 5;
    const int lane = tid & 31;

    const int r0 = cta * ROWS_PER_CTA;
    int r1 = r0 + ROWS_PER_CTA; if (r1 > N_NODES) r1 = N_NODES;

    // ---- phase 0: v0[n] = sum_f x[n,f], warp per node ----
    for (int n = r0 + wid; n < r1; n += 32) {
        const float4* xr = reinterpret_cast<const float4*>(x + (size_t)n * F_IN);
        float4 v = __ldg(&xr[lane]);
        float s = v.x + v.y + v.z + v.w;
        #pragma unroll
        for (int o = 16; o; o >>= 1) s += __shfl_xor_sync(0xffffffffu, s, o);
        if (lane == 0) g_s[n] = s;
    }
    grid_barrier(1);

    // ---- phases 1..25: power iterations ----
    for (int p = 1; p <= MAX_POWER; p++) {
        // fill smem with the full previous power vector (coalesced float4)
        const float4* vin4 = reinterpret_cast<const float4*>(g_s + (size_t)(p - 1) * N_NODES);
        float4*       sv4  = reinterpret_cast<float4*>(sv);
        #pragma unroll 4
        for (int i = tid; i < N_NODES / 4; i += T_P)
            sv4[i] = __ldg(&vin4[i]);
        __syncthreads();

        float* __restrict__ vout = g_s + (size_t)p * N_NODES;
        for (int row = r0 + wid; row < r1; row += 32) {
            int beg = __ldg(&g_rowptr[row]);
            int end = __ldg(&g_rowptr[row + 1]);
            float acc = 0.0f;
            for (int i = beg + lane; i < end; i += 32) {
                int2 e = __ldg(&g_csr[i]);
                acc += __int_as_float(e.y) * sv[e.x];
            }
            #pragma unroll
            for (int o = 16; o; o >>= 1) acc += __shfl_xor_sync(0xffffffffu, acc, o);
            if (lane == 0) vout[row] = acc;
        }
        grid_barrier(1 + p);
    }

    // ---- output phase: y[n,o] = sum_k coeff[o,k] * s[1 + o*(K-1) + k][n] ----
    for (int n = r0 + tid; n < r1; n += T_P) {
        float svv[MAX_POWER];
        #pragma unroll
        for (int p = 0; p < MAX_POWER; p++)
            svv[p] = g_s[(size_t)(p + 1) * N_NODES + n];
        #pragma unroll
        for (int o = 0; o < F_OUT; o++) {
            float acc = 0.0f;
            #pragma unroll
            for (int k = 0; k < K_TAPS; k++)
                acc += __ldg(&coeff[o * K_TAPS + k]) * svv[o * (K_TAPS - 1) + k];
            y[(size_t)n * F_OUT + o] = acc;
        }
    }
}

// ---------------------------------------------------------------------------
extern "C" void kernel_launch(void* const* d_in, const int* in_sizes, int n_in,
                              void* d_out, int out_size) {
    const float* x     = (const float*)d_in[0];
    const int*   rows  = (const int*)  d_in[1];
    const int*   cols  = (const int*)  d_in[2];
    const float* vals  = (const float*)d_in[3];
    const float* coeff = (const float*)d_in[4];
    float*       y     = (float*)d_out;

    // opt-in to >48KB dynamic smem (idempotent, immediate API — not captured)
    cudaFuncSetAttribute(gfl_persist_kernel,
                         cudaFuncAttributeMaxDynamicSharedMemorySize, SMEM_BYTES);

    const int T = 256;
    const int edge_blocks = (N_EDGES + T - 1) / T;

    gfl_hist_kernel   <<<edge_blocks, T>>>(rows);
    gfl_scan_kernel   <<<1, SCAN_T>>>();
    gfl_scatter_kernel<<<edge_blocks, T>>>(rows, cols, vals);

    gfl_persist_kernel<<<GRID_P, T_P, SMEM_BYTES>>>(x, coeff, y);
}

// round 7
// speedup vs baseline: 1.8173x; 1.8173x over previous
#include <cuda_runtime.h>
#include <cuda_bf16.h>

#define N_NODES   50000
#define N_EDGES   1600000
#define F_IN      128
#define F_OUT     8
#define K_TAPS    4
#define MAX_POWER 25            // F_OUT*(K_TAPS-1)+1
#define SCAN_T    1024

#define GRID_P    148           // persistent grid: 1 CTA/SM, all co-resident
#define T_P       1024
#define ROWS_PER_CTA ((N_NODES + GRID_P - 1) / GRID_P)   // 338
#define SMEM_BYTES (N_NODES * 4)                          // 200 KB

// ---- device-global scratch ----
__device__ float    g_s[(MAX_POWER + 1) * N_NODES];   // power vectors, 5.2 MB
__device__ int      g_cnt[N_NODES];
__device__ int      g_rowptr[N_NODES + 1];
__device__ int      g_fill[N_NODES];
__device__ int2     g_csr[N_EDGES];                   // packed {col, val-bits}
__device__ unsigned g_arrive;                         // barrier arrivals (monotonic)
__device__ unsigned g_epoch;                          // completed-epoch counter

// ---------------------------------------------------------------------------
// Kernel 1: histogram of destination rows. (g_cnt == 0 at entry: invariant.)
// ---------------------------------------------------------------------------
__global__ void gfl_hist_kernel(const int* __restrict__ rows) {
    int e = blockIdx.x * blockDim.x + threadIdx.x;
    if (e < N_EDGES) atomicAdd(&g_cnt[__ldg(&rows[e])], 1);
}

// ---------------------------------------------------------------------------
// Kernel 2: single-block exclusive scan -> rowptr + fill cursors.
// Re-zeros g_cnt and resets the barrier state for graph-replay determinism.
// ---------------------------------------------------------------------------
__global__ void gfl_scan_kernel() {
    __shared__ int part[SCAN_T];
    int t = threadIdx.x;
    const int CH = (N_NODES + SCAN_T - 1) / SCAN_T;       // 49
    int beg = t * CH;
    int end = beg + CH; if (end > N_NODES) end = N_NODES;

    int s = 0;
    for (int i = beg; i < end; i++) s += g_cnt[i];
    part[t] = s;
    __syncthreads();

    #pragma unroll
    for (int off = 1; off < SCAN_T; off <<= 1) {
        int v = (t >= off) ? part[t - off] : 0;
        __syncthreads();
        part[t] += v;
        __syncthreads();
    }
    int run = (t == 0) ? 0 : part[t - 1];                 // exclusive prefix

    for (int i = beg; i < end; i++) {
        int c = g_cnt[i];
        g_rowptr[i] = run;
        g_fill[i]   = run;
        g_cnt[i]    = 0;            // restore invariant for next call
        run += c;
    }
    if (t == SCAN_T - 1) {
        g_rowptr[N_NODES] = run;
        g_arrive = 0u;
        g_epoch  = 0u;
    }
}

// ---------------------------------------------------------------------------
// Kernel 3: scatter edges into CSR slots.
// ---------------------------------------------------------------------------
__global__ void gfl_scatter_kernel(const int*   __restrict__ rows,
                                   const int*   __restrict__ cols,
                                   const float* __restrict__ vals) {
    int e = blockIdx.x * blockDim.x + threadIdx.x;
    if (e >= N_EDGES) return;
    int r   = __ldg(&rows[e]);
    int pos = atomicAdd(&g_fill[r], 1);
    int2 pk;
    pk.x = __ldg(&cols[e]);
    pk.y = __float_as_int(__ldg(&vals[e]));
    g_csr[pos] = pk;
}

// ---------------------------------------------------------------------------
// Device-wide barrier: one atomic arrive per CTA; LAST arriver publishes the
// epoch; everyone else spins on a PLAIN LOAD (no RMW serialization).
// `target` is the 1-based barrier index within this launch.
// ---------------------------------------------------------------------------
__device__ __forceinline__ void grid_barrier(unsigned target) {
    __syncthreads();
    if (threadIdx.x == 0) {
        __threadfence();                               // release this CTA's writes
        unsigned arrived = atomicAdd(&g_arrive, 1u) + 1u;
        if (arrived == target * GRID_P) {
            __threadfence();
            *(volatile unsigned*)&g_epoch = target;    // publish epoch
        } else {
            while (*(volatile unsigned*)&g_epoch < target) __nanosleep(64);
        }
        __threadfence();                               // acquire
    }
    __syncthreads();
}

// ---------------------------------------------------------------------------
// Kernel 4 (persistent): rowsum -> 25x (smem fill + CSR SpMV + barrier) -> taps
// smem holds the entire current power vector (200 KB). 8 lanes per row,
// shuffles restricted to the 8-lane sub-group mask (sub-warps can diverge
// in row-loop trip count at the r1 boundary; full-warp masks would hang).
// ---------------------------------------------------------------------------
__global__ void __launch_bounds__(T_P, 1)
gfl_persist_kernel(const float* __restrict__ x,
                   const float* __restrict__ coeff,
                   float*       __restrict__ y) {
    extern __shared__ float sv[];                 // N_NODES floats
    const int tid  = threadIdx.x;
    const int wid  = tid >> 5;
    const int lane = tid & 31;
    const int sub  = lane >> 3;                   // sub-warp 0..3 (8 lanes each)
    const int sl   = lane & 7;
    const unsigned submask = 0xFFu << (sub * 8);  // this sub-warp's lanes

    const int r0 = blockIdx.x * ROWS_PER_CTA;
    int r1 = r0 + ROWS_PER_CTA; if (r1 > N_NODES) r1 = N_NODES;

    // ---- phase 0: v0[n] = sum_f x[n,f], warp per node ----
    for (int n = r0 + wid; n < r1; n += 32) {
        const float4* xr = reinterpret_cast<const float4*>(x + (size_t)n * F_IN);
        float4 v = __ldg(&xr[lane]);
        float s = v.x + v.y + v.z + v.w;
        #pragma unroll
        for (int o = 16; o; o >>= 1) s += __shfl_xor_sync(0xffffffffu, s, o);
        if (lane == 0) g_s[n] = s;
    }
    grid_barrier(1);

    // ---- phases 1..25: power iterations ----
    for (int p = 1; p <= MAX_POWER; p++) {
        // fill smem with the full previous power vector (coalesced float4)
        const float4* vin4 = reinterpret_cast<const float4*>(g_s + (size_t)(p - 1) * N_NODES);
        float4*       sv4  = reinterpret_cast<float4*>(sv);
        #pragma unroll 4
        for (int i = tid; i < N_NODES / 4; i += T_P)
            sv4[i] = __ldg(&vin4[i]);
        __syncthreads();

        float* __restrict__ vout = g_s + (size_t)p * N_NODES;
        // 8 lanes per row: each warp covers 4 rows per trip
        for (int row = r0 + wid * 4 + sub; row < r1; row += 32 * 4) {
            int beg = __ldg(&g_rowptr[row]);
            int end = __ldg(&g_rowptr[row + 1]);
            float acc = 0.0f;
            for (int i = beg + sl; i < end; i += 8) {
                int2 e = __ldg(&g_csr[i]);
                acc += __int_as_float(e.y) * sv[e.x];
            }
            // reduction within the 8-lane sub-group only
            acc += __shfl_xor_sync(submask, acc, 4);
            acc += __shfl_xor_sync(submask, acc, 2);
            acc += __shfl_xor_sync(submask, acc, 1);
            if (sl == 0) vout[row] = acc;
        }
        grid_barrier(1 + p);
    }

    // ---- output phase: y[n,o] = sum_k coeff[o,k] * s[1 + o*(K-1) + k][n] ----
    for (int n = r0 + tid; n < r1; n += T_P) {
        float svv[MAX_POWER];
        #pragma unroll
        for (int p = 0; p < MAX_POWER; p++)
            svv[p] = g_s[(size_t)(p + 1) * N_NODES + n];
        #pragma unroll
        for (int o = 0; o < F_OUT; o++) {
            float acc = 0.0f;
            #pragma unroll
            for (int k = 0; k < K_TAPS; k++)
                acc += __ldg(&coeff[o * K_TAPS + k]) * svv[o * (K_TAPS - 1) + k];
            y[(size_t)n * F_OUT + o] = acc;
        }
    }
}

// ---------------------------------------------------------------------------
extern "C" void kernel_launch(void* const* d_in, const int* in_sizes, int n_in,
                              void* d_out, int out_size) {
    const float* x     = (const float*)d_in[0];
    const int*   rows  = (const int*)  d_in[1];
    const int*   cols  = (const int*)  d_in[2];
    const float* vals  = (const float*)d_in[3];
    const float* coeff = (const float*)d_in[4];
    float*       y     = (float*)d_out;

    cudaFuncSetAttribute(gfl_persist_kernel,
                         cudaFuncAttributeMaxDynamicSharedMemorySize, SMEM_BYTES);

    const int T = 256;
    const int edge_blocks = (N_EDGES + T - 1) / T;

    gfl_hist_kernel   <<<edge_blocks, T>>>(rows);
    gfl_scan_kernel   <<<1, SCAN_T>>>();
    gfl_scatter_kernel<<<edge_blocks, T>>>(rows, cols, vals);

    gfl_persist_kernel<<<GRID_P, T_P, SMEM_BYTES>>>(x, coeff, y);
}

// round 11
// speedup vs baseline: 2.2258x; 1.2248x over previous
#include <cuda_runtime.h>
#include <cuda_bf16.h>

#define N_NODES   50000
#define N_EDGES   1600000
#define F_IN      128
#define F_OUT     8
#define K_TAPS    4
#define MAX_POWER 25            // F_OUT*(K_TAPS-1)+1

#define GRID_P    148           // persistent grid: 1 CTA/SM, all co-resident
#define T_P       1024
#define ROWS_PER_CTA ((N_NODES + GRID_P - 1) / GRID_P)   // 338
#define SMEM_BYTES (N_NODES * 4)                          // 200 KB dynamic

// ---- device-global scratch ----
__device__ __align__(16) float g_s[(MAX_POWER + 1) * N_NODES];  // 5.2 MB
__device__ int      g_cnt[N_NODES];
__device__ int      g_rowptr[N_NODES + 1];
__device__ int      g_fill[N_NODES];
__device__ int2     g_csr[N_EDGES];                   // packed {col, val-bits}
__device__ int      g_part[GRID_P];                   // per-CTA edge-count partials
__device__ unsigned g_arrive;                         // barrier arrivals (monotonic)
__device__ unsigned g_epoch;                          // completed-epoch counter
__device__ unsigned g_done;                           // end-of-kernel reset counter

// ---------------------------------------------------------------------------
// Device-wide barrier: one atomic arrive per CTA; LAST arriver publishes the
// epoch; everyone else spins on a PLAIN LOAD (no RMW serialization).
// ---------------------------------------------------------------------------
__device__ __forceinline__ void grid_barrier(unsigned target) {
    __syncthreads();
    if (threadIdx.x == 0) {
        __threadfence();                               // release this CTA's writes
        unsigned arrived = atomicAdd(&g_arrive, 1u) + 1u;
        if (arrived == target * GRID_P) {
            __threadfence();
            *(volatile unsigned*)&g_epoch = target;    // publish epoch
        } else {
            while (*(volatile unsigned*)&g_epoch < target) __nanosleep(32);
        }
        __threadfence();                               // acquire
    }
    __syncthreads();
}

// ---------------------------------------------------------------------------
// ONE fused persistent kernel: CSR build + rowsum + 25 power iters + output.
// smem holds the entire current power vector (200 KB).
// ---------------------------------------------------------------------------
__global__ void __launch_bounds__(T_P, 1)
gfl_fused_kernel(const float* __restrict__ x,
                 const int*   __restrict__ rows,
                 const int*   __restrict__ cols,
                 const float* __restrict__ vals,
                 const float* __restrict__ coeff,
                 float*       __restrict__ y) {
    extern __shared__ float sv[];                 // N_NODES floats (dynamic)
    __shared__ int scanbuf[512];
    __shared__ int s_base;

    const int tid  = threadIdx.x;
    const int wid  = tid >> 5;
    const int lane = tid & 31;
    const int sub  = lane >> 3;                   // 8-lane sub-group 0..3
    const int sl   = lane & 7;
    const unsigned submask = 0xFFu << (sub * 8);
    const int cta  = blockIdx.x;

    const int r0 = cta * ROWS_PER_CTA;
    int r1 = r0 + ROWS_PER_CTA; if (r1 > N_NODES) r1 = N_NODES;
    const int nrows = r1 - r0;
    unsigned bar = 0;

    // ---- phase A: zero this chunk's counters + rowsum v0 (warp per node) ----
    for (int i = r0 + tid; i < r1; i += T_P) g_cnt[i] = 0;
    for (int n = r0 + wid; n < r1; n += 32) {
        const float4* xr = reinterpret_cast<const float4*>(x + (size_t)n * F_IN);
        float4 v = __ldg(&xr[lane]);
        float s = v.x + v.y + v.z + v.w;
        #pragma unroll
        for (int o = 16; o; o >>= 1) s += __shfl_xor_sync(0xffffffffu, s, o);
        if (lane == 0) g_s[n] = s;
    }
    grid_barrier(++bar);

    // ---- phase B: histogram of destination rows (all CTAs) ----
    for (int e = cta * T_P + tid; e < N_EDGES; e += GRID_P * T_P)
        atomicAdd(&g_cnt[__ldg(&rows[e])], 1);
    grid_barrier(++bar);

    // ---- phase C1: block-local inclusive scan of this chunk's row counts ----
    int myc = 0;
    if (tid < 512) {
        myc = (tid < nrows) ? g_cnt[r0 + tid] : 0;
        scanbuf[tid] = myc;
    }
    __syncthreads();
    #pragma unroll
    for (int off = 1; off < 512; off <<= 1) {
        int v = 0;
        if (tid < 512 && tid >= off) v = scanbuf[tid - off];
        __syncthreads();
        if (tid < 512) scanbuf[tid] += v;
        __syncthreads();
    }
    if (tid == 0) g_part[cta] = scanbuf[511];
    grid_barrier(++bar);

    // ---- phase C2: prefix of partials -> rowptr + fill cursors ----
    if (tid == 0) {
        int b = 0;
        #pragma unroll 4
        for (int i = 0; i < cta; i++) b += g_part[i];
        s_base = b;
        if (cta == 0) g_rowptr[N_NODES] = N_EDGES;
    }
    __syncthreads();
    if (tid < nrows) {
        int v = s_base + scanbuf[tid] - myc;      // exclusive prefix
        g_rowptr[r0 + tid] = v;
        g_fill[r0 + tid]   = v;
    }
    grid_barrier(++bar);

    // ---- phase D: scatter edges into CSR slots (all CTAs) ----
    for (int e = cta * T_P + tid; e < N_EDGES; e += GRID_P * T_P) {
        int r   = __ldg(&rows[e]);
        int pos = atomicAdd(&g_fill[r], 1);
        int2 pk;
        pk.x = __ldg(&cols[e]);
        pk.y = __float_as_int(__ldg(&vals[e]));
        g_csr[pos] = pk;
    }
    grid_barrier(++bar);

    // ---- phase E: 25 power iterations (smem-resident vector) ----
    for (int p = 1; p <= MAX_POWER; p++) {
        const float4* vin4 = reinterpret_cast<const float4*>(g_s + (size_t)(p - 1) * N_NODES);
        float4*       sv4  = reinterpret_cast<float4*>(sv);
        #pragma unroll 4
        for (int i = tid; i < N_NODES / 4; i += T_P)
            sv4[i] = __ldg(&vin4[i]);
        __syncthreads();

        float* __restrict__ vout = g_s + (size_t)p * N_NODES;
        // 8 lanes per row; shuffles restricted to the sub-group mask
        for (int row = r0 + wid * 4 + sub; row < r1; row += 32 * 4) {
            int beg = __ldg(&g_rowptr[row]);
            int end = __ldg(&g_rowptr[row + 1]);
            float acc = 0.0f;
            for (int i = beg + sl; i < end; i += 8) {
                int2 e = __ldg(&g_csr[i]);
                acc += __int_as_float(e.y) * sv[e.x];
            }
            acc += __shfl_xor_sync(submask, acc, 4);
            acc += __shfl_xor_sync(submask, acc, 2);
            acc += __shfl_xor_sync(submask, acc, 1);
            if (sl == 0) vout[row] = acc;
        }
        grid_barrier(++bar);
    }

    // ---- phase F: y[n,o] = sum_k coeff[o,k] * s[1 + o*(K-1) + k][n] ----
    for (int n = r0 + tid; n < r1; n += T_P) {
        float svv[MAX_POWER];
        #pragma unroll
        for (int p = 0; p < MAX_POWER; p++)
            svv[p] = g_s[(size_t)(p + 1) * N_NODES + n];
        #pragma unroll
        for (int o = 0; o < F_OUT; o++) {
            float acc = 0.0f;
            #pragma unroll
            for (int k = 0; k < K_TAPS; k++)
                acc += __ldg(&coeff[o * K_TAPS + k]) * svv[o * (K_TAPS - 1) + k];
            y[(size_t)n * F_OUT + o] = acc;
        }
    }

    // ---- reset barrier state for the next launch/replay.
    // Every CTA is past the final grid_barrier before it increments g_done,
    // so when the LAST increment happens no CTA can still be spinning.
    __syncthreads();
    if (tid == 0) {
        __threadfence();
        unsigned old = atomicAdd(&g_done, 1u);
        if (old == GRID_P - 1) {
            g_arrive = 0u;
            g_epoch  = 0u;
            g_done   = 0u;
            __threadfence();
        }
    }
}

// ---------------------------------------------------------------------------
extern "C" void kernel_launch(void* const* d_in, const int* in_sizes, int n_in,
                              void* d_out, int out_size) {
    const float* x     = (const float*)d_in[0];
    const int*   rows  = (const int*)  d_in[1];
    const int*   cols  = (const int*)  d_in[2];
    const float* vals  = (const float*)d_in[3];
    const float* coeff = (const float*)d_in[4];
    float*       y     = (float*)d_out;

    cudaFuncSetAttribute(gfl_fused_kernel,
                         cudaFuncAttributeMaxDynamicSharedMemorySize, SMEM_BYTES);

    gfl_fused_kernel<<<GRID_P, T_P, SMEM_BYTES>>>(x, rows, cols, vals, coeff, y);
}